// round 17
// baseline (speedup 1.0000x reference)
#include <cuda_runtime.h>
#include <cuda_fp16.h>
#include <cstdint>

// ---------------- problem shape ----------------
static constexpr int B_ = 8;
static constexpr int T_ = 2048;
static constexpr int C_ = 1024;
static constexpr int H_ = 1024;

// ---------------- scratch (__device__ globals) ----------------
__device__ __half g_xh[(size_t)B_ * T_ * C_];
__device__ __half g_xl[(size_t)B_ * T_ * C_];
__device__ __half g_wqth[(size_t)C_ * H_];
__device__ __half g_wqtl[(size_t)C_ * H_];
__device__ __half g_wkth[(size_t)C_ * H_];
__device__ __half g_wktl[(size_t)C_ * H_];
__device__ float  g_mtp[(size_t)4 * C_ * C_];
__device__ __half g_mth[(size_t)C_ * C_];
__device__ __half g_mtl[(size_t)C_ * C_];
__device__ __half g_uh[(size_t)B_ * T_ * C_];
__device__ __half g_ul[(size_t)B_ * T_ * C_];
__device__ __half g_wvh[(size_t)H_ * C_];
__device__ __half g_vth[(size_t)B_ * H_ * T_];
__device__ __half g_weih[(size_t)B_ * T_ * T_];

// ---------------- helpers ----------------
__device__ __forceinline__ uint32_t pack2(__half a, __half b) {
    __half2 h2 = __halves2half2(a, b);
    return *reinterpret_cast<uint32_t*>(&h2);
}
__device__ __forceinline__ void cpa16(uint32_t dst, const void* src) {
    asm volatile("cp.async.cg.shared.global [%0], [%1], 16;" :: "r"(dst), "l"(src));
}
__device__ __forceinline__ void cp_commit() {
    asm volatile("cp.async.commit_group;" ::: "memory");
}
template <int N>
__device__ __forceinline__ void cp_wait() {
    asm volatile("cp.async.wait_group %0;" :: "n"(N) : "memory");
}
__device__ __forceinline__ uint32_t smem_u32(const void* p) {
    uint32_t a;
    asm("{ .reg .u64 t; cvta.to.shared.u64 t, %1; cvt.u32.u64 %0, t; }" : "=r"(a) : "l"(p));
    return a;
}
__device__ __forceinline__ void mma16(float* d, uint32_t a0, uint32_t a1, uint32_t a2,
                                      uint32_t a3, uint32_t b0, uint32_t b1) {
    asm volatile(
        "mma.sync.aligned.m16n8k16.row.col.f32.f16.f16.f32 "
        "{%0,%1,%2,%3},{%4,%5,%6,%7},{%8,%9},{%0,%1,%2,%3};"
        : "+f"(d[0]), "+f"(d[1]), "+f"(d[2]), "+f"(d[3])
        : "r"(a0), "r"(a1), "r"(a2), "r"(a3), "r"(b0), "r"(b1));
}
__device__ __forceinline__ int pperm(int c) {
    const int p = (c & 31) >> 1;
    const int pp = ((p & 3) << 2) | (p >> 2);
    return (c & ~31) | (pp << 1) | (c & 1);
}

// ---------------- FP16 multi-pass NT GEMM via mma.sync (pair-permuted operands) ----------------
static constexpr int GEMM_SMEM = 2 * 32768;

template <int EPI, int PASSES>
__global__ __launch_bounds__(256, 2)
void mma_nt(const __half* __restrict__ Ahi, const __half* __restrict__ Alo,
            const __half* __restrict__ Bhi, const __half* __restrict__ Blo,
            float* __restrict__ Cf, __half* __restrict__ Ch, __half* __restrict__ Cl,
            int K, int lda, int ldb, int ldc,
            long long sA, long long sB, long long sC,
            float alpha, int causal)
{
    extern __shared__ char smc[];
    const int bn = blockIdx.x, bz = blockIdx.z;
    int bm = blockIdx.y;
    if (causal == 1 && bn > bm) return;
    if (causal == 2) bm = gridDim.y - 1 - bm;
    int Keff = K;
    if (causal == 2) { int kl = (bm + 1) * 128; Keff = kl < K ? kl : K; }
    const int nk = Keff / 32;

    const __half* Ah = Ahi + (size_t)bz * sA;
    const __half* Al = (PASSES >= 2) ? Alo + (size_t)bz * sA : nullptr;
    const __half* Bh = Bhi + (size_t)bz * sB;
    const __half* Bl = (PASSES == 3) ? Blo + (size_t)bz * sB : nullptr;

    const int tid = threadIdx.x;
    const int lane = tid & 31, w = tid >> 5;
    const int wm = w & 1, wn = w >> 1;
    const int gr = lane >> 2, tc = lane & 3;
    const uint32_t sbase = smem_u32(smc);

    auto load_stage = [&](int kt, int s) {
        const int k0 = kt * 32;
        const uint32_t dst = sbase + (uint32_t)s * 32768u;
#pragma unroll
        for (int t = 0; t < 2; t++) {
            const int idx = t * 256 + tid;
            const int row = idx >> 2, j = (idx & 3) * 8;
            const uint32_t off = (uint32_t)(row * 64 + j * 2);
            const size_t ga = (size_t)(bm * 128 + row) * lda + k0 + j;
            const size_t gb = (size_t)(bn * 128 + row) * ldb + k0 + j;
            cpa16(dst + off,           Ah + ga);
            if (PASSES >= 2) cpa16(dst + 8192u + off, Al + ga);
            cpa16(dst + 16384u + off,  Bh + gb);
            if (PASSES == 3) cpa16(dst + 24576u + off, Bl + gb);
        }
        cp_commit();
    };

    float acc[4][4][4];
#pragma unroll
    for (int i = 0; i < 4; i++)
#pragma unroll
        for (int j = 0; j < 4; j++)
#pragma unroll
            for (int r = 0; r < 4; r++) acc[i][j][r] = 0.f;

    load_stage(0, 0);

    const int rbA = (wm * 64 + gr) * 4 + tc;
    const int rbB = (wn * 32 + gr) * 4 + tc;

    for (int kt = 0; kt < nk; kt++) {
        const int s = kt & 1;
        cp_wait<0>();
        __syncthreads();
        if (kt + 1 < nk) load_stage(kt + 1, s ^ 1);

        const uint4* S   = (const uint4*)(smc + s * 32768);
        const uint4* pAh = S;
        const uint4* pAl = S + 512;
        const uint4* pBh = S + 1024;
        const uint4* pBl = S + 1536;

        uint4 bh0 = pBh[rbB], bh1 = pBh[rbB + 32], bh2 = pBh[rbB + 64], bh3 = pBh[rbB + 96];

#pragma unroll
        for (int fm = 0; fm < 4; fm++) {
            const int ra = rbA + fm * 64;
            uint4 a0 = pAh[ra], a8 = pAh[ra + 32];
            uint4 l0, l8;
            if (PASSES >= 2) { l0 = pAl[ra]; l8 = pAl[ra + 32]; }
#pragma unroll
            for (int fn = 0; fn < 4; fn++) {
                const uint4 bh = fn == 0 ? bh0 : fn == 1 ? bh1 : fn == 2 ? bh2 : bh3;
                float* a = acc[fm][fn];
                mma16(a, a0.x, a8.x, a0.y, a8.y, bh.x, bh.y);
                if (PASSES >= 2) mma16(a, l0.x, l8.x, l0.y, l8.y, bh.x, bh.y);
                mma16(a, a0.z, a8.z, a0.w, a8.w, bh.z, bh.w);
                if (PASSES >= 2) mma16(a, l0.z, l8.z, l0.w, l8.w, bh.z, bh.w);
            }
        }

        if (PASSES == 3) {
            uint4 bl0 = pBl[rbB], bl1 = pBl[rbB + 32], bl2 = pBl[rbB + 64], bl3 = pBl[rbB + 96];
#pragma unroll
            for (int fm = 0; fm < 4; fm++) {
                const int ra = rbA + fm * 64;
                uint4 a0 = pAh[ra], a8 = pAh[ra + 32];
#pragma unroll
                for (int fn = 0; fn < 4; fn++) {
                    const uint4 bl = fn == 0 ? bl0 : fn == 1 ? bl1 : fn == 2 ? bl2 : bl3;
                    float* a = acc[fm][fn];
                    mma16(a, a0.x, a8.x, a0.y, a8.y, bl.x, bl.y);
                    mma16(a, a0.z, a8.z, a0.w, a8.w, bl.z, bl.w);
                }
            }
        }
    }

#pragma unroll
    for (int fm = 0; fm < 4; fm++) {
        const int r0 = bm * 128 + wm * 64 + fm * 16 + gr;
#pragma unroll
        for (int fn = 0; fn < 4; fn++) {
            const int c0 = bn * 128 + wn * 32 + fn * 8 + 2 * tc;
            const size_t b0 = (size_t)bz * sC + (size_t)r0 * ldc;
            const size_t b8 = b0 + (size_t)8 * ldc;
            const float* a = acc[fm][fn];
            if (EPI == 0) {
                *(float2*)(Cf + b0 + c0) = make_float2(a[0] * alpha, a[1] * alpha);
                *(float2*)(Cf + b8 + c0) = make_float2(a[2] * alpha, a[3] * alpha);
            } else {
                const int cp = pperm(c0);
                __half h0 = __float2half_rn(a[0]), h1 = __float2half_rn(a[1]);
                __half h2 = __float2half_rn(a[2]), h3 = __float2half_rn(a[3]);
                *(__half2*)(Ch + b0 + cp) = __halves2half2(h0, h1);
                *(__half2*)(Ch + b8 + cp) = __halves2half2(h2, h3);
                if (EPI == 1) {
                    *(__half2*)(Cl + b0 + cp) = __halves2half2(
                        __float2half_rn(a[0] - __half2float(h0)),
                        __float2half_rn(a[1] - __half2float(h1)));
                    *(__half2*)(Cl + b8 + cp) = __halves2half2(
                        __float2half_rn(a[2] - __half2float(h2)),
                        __float2half_rn(a[3] - __half2float(h3)));
                }
            }
        }
    }
}

// ---------------- elementwise fp16 split, pair-permuted layout ----------------
__global__ void split_kernel(const float* __restrict__ src,
                             __half* __restrict__ hi, __half* __restrict__ lo, int n8)
{
    const int i = blockIdx.x * blockDim.x + threadIdx.x;
    if (i >= n8) return;
    const int u = i & 3;
    const int blk = (i >> 2) * 32;
    uint32_t ho[4], lw[4];
#pragma unroll
    for (int b = 0; b < 4; b++) {
        const float2 v = *(const float2*)(src + blk + 8 * b + 2 * u);
        __half h0 = __float2half_rn(v.x), h1 = __float2half_rn(v.y);
        ho[b] = pack2(h0, h1);
        lw[b] = pack2(__float2half_rn(v.x - __half2float(h0)),
                      __float2half_rn(v.y - __half2float(h1)));
    }
    ((uint2*)(hi + blk))[u * 2 + 0] = make_uint2(ho[0], ho[1]);
    ((uint2*)(hi + blk))[u * 2 + 1] = make_uint2(ho[2], ho[3]);
    if (lo) {
        ((uint2*)(lo + blk))[u * 2 + 0] = make_uint2(lw[0], lw[1]);
        ((uint2*)(lo + blk))[u * 2 + 1] = make_uint2(lw[2], lw[3]);
    }
}

// ---------------- Mt split-K reduce + permuted fp16 hi/lo split ----------------
__global__ void mt_reduce_split(const float* __restrict__ p,
                                __half* __restrict__ hi, __half* __restrict__ lo, int n8)
{
    const int i = blockIdx.x * blockDim.x + threadIdx.x;
    if (i >= n8) return;
    const size_t CC = (size_t)C_ * C_;
    const int u = i & 3;
    const int blk = (i >> 2) * 32;
    uint32_t ho[4], lw[4];
#pragma unroll
    for (int b = 0; b < 4; b++) {
        const size_t o = (size_t)blk + 8 * b + 2 * u;
        float2 v0 = *(const float2*)(p + o);
        float2 v1 = *(const float2*)(p + CC + o);
        float2 v2 = *(const float2*)(p + 2 * CC + o);
        float2 v3 = *(const float2*)(p + 3 * CC + o);
        float x = (v0.x + v1.x) + (v2.x + v3.x);
        float y = (v0.y + v1.y) + (v2.y + v3.y);
        __half h0 = __float2half_rn(x), h1 = __float2half_rn(y);
        ho[b] = pack2(h0, h1);
        lw[b] = pack2(__float2half_rn(x - __half2float(h0)),
                      __float2half_rn(y - __half2float(h1)));
    }
    ((uint2*)(hi + blk))[u * 2 + 0] = make_uint2(ho[0], ho[1]);
    ((uint2*)(hi + blk))[u * 2 + 1] = make_uint2(ho[2], ho[3]);
    ((uint2*)(lo + blk))[u * 2 + 0] = make_uint2(lw[0], lw[1]);
    ((uint2*)(lo + blk))[u * 2 + 1] = make_uint2(lw[2], lw[3]);
}

// ---------------- fused dual transpose + fp16 split ----------------
__global__ __launch_bounds__(256)
void transpose_split2_kernel(const float* __restrict__ W0,
                             __half* __restrict__ t0h, __half* __restrict__ t0l,
                             const float* __restrict__ W1,
                             __half* __restrict__ t1h, __half* __restrict__ t1l,
                             int Hd, int Cd)
{
    const float* W = (blockIdx.z == 0) ? W0 : W1;
    __half* th = (blockIdx.z == 0) ? t0h : t1h;
    __half* tl = (blockIdx.z == 0) ? t0l : t1l;

    __shared__ float tile[64][33];
    const int c0 = blockIdx.x * 32, h0 = blockIdx.y * 64;
    const int tid = threadIdx.x;
    {
        const int lc = tid & 31;
        const int lh = tid >> 5;
#pragma unroll
        for (int i = 0; i < 8; i++)
            tile[lh + 8 * i][lc] = W[(size_t)(h0 + lh + 8 * i) * Cd + c0 + lc];
    }
    __syncthreads();
    const int lc = tid >> 3;
    const int lp = tid & 7;
#pragma unroll
    for (int i = 0; i < 4; i++) {
        const int p = lp + 8 * i;
        const int b = p >> 4;
        const int pin = p & 15;
        const int ppin = ((pin & 3) << 2) | (pin >> 2);
        const int hs = p * 2;
        const float v0 = tile[hs][lc], v1 = tile[hs + 1][lc];
        const __half h0_ = __float2half_rn(v0), h1_ = __float2half_rn(v1);
        const size_t o = (size_t)(c0 + lc) * Hd + h0 + b * 32 + ppin * 2;
        *(__half2*)(th + o) = __halves2half2(h0_, h1_);
        *(__half2*)(tl + o) = __halves2half2(__float2half_rn(v0 - __half2float(h0_)),
                                             __float2half_rn(v1 - __half2float(h1_)));
    }
}

// ---------------- single-sweep causal softmax + fp16 hi write (permuted cols) ----------------
__global__ __launch_bounds__(256)
void softmax_split_kernel(float* __restrict__ W, __half* __restrict__ Wh, int T)
{
    const long long row = blockIdx.x;
    const int t = (int)(row % T);
    float* p   = W  + row * (long long)T;
    __half* ph = Wh + row * (long long)T;
    const int n = t + 1;
    const int tid = threadIdx.x;
    const int base = tid * 8;

    __shared__ float red[8];

    float v[8];
    if (base + 7 < n) {
        float4 a = *(const float4*)(p + base);
        float4 b = *(const float4*)(p + base + 4);
        v[0] = a.x; v[1] = a.y; v[2] = a.z; v[3] = a.w;
        v[4] = b.x; v[5] = b.y; v[6] = b.z; v[7] = b.w;
    } else {
#pragma unroll
        for (int j = 0; j < 8; j++)
            v[j] = (base + j < n) ? p[base + j] : -3.4e38f;
    }

    float m = v[0];
#pragma unroll
    for (int j = 1; j < 8; j++) m = fmaxf(m, v[j]);
#pragma unroll
    for (int o = 16; o; o >>= 1) m = fmaxf(m, __shfl_xor_sync(0xffffffffu, m, o));
    if ((tid & 31) == 0) red[tid >> 5] = m;
    __syncthreads();
    if (tid < 32) {
        float mb = (tid < 8) ? red[tid] : -3.4e38f;
#pragma unroll
        for (int o = 4; o; o >>= 1) mb = fmaxf(mb, __shfl_xor_sync(0xffffffffu, mb, o));
        if (tid == 0) red[0] = mb;
    }
    __syncthreads();
    m = red[0];
    __syncthreads();

    float s = 0.f;
#pragma unroll
    for (int j = 0; j < 8; j++) {
        v[j] = (base + j < n) ? __expf(v[j] - m) : 0.f;
        s += v[j];
    }
#pragma unroll
    for (int o = 16; o; o >>= 1) s += __shfl_xor_sync(0xffffffffu, s, o);
    if ((tid & 31) == 0) red[tid >> 5] = s;
    __syncthreads();
    if (tid < 32) {
        float sb = (tid < 8) ? red[tid] : 0.f;
#pragma unroll
        for (int o = 4; o; o >>= 1) sb += __shfl_xor_sync(0xffffffffu, sb, o);
        if (tid == 0) red[0] = sb;
    }
    __syncthreads();
    const float inv = 1.f / red[0];

#pragma unroll
    for (int j = 0; j < 8; j++) v[j] *= inv;
    *(float4*)(p + base)     = make_float4(v[0], v[1], v[2], v[3]);
    *(float4*)(p + base + 4) = make_float4(v[4], v[5], v[6], v[7]);

    const int u = tid & 3;
    __half* phb = ph + (base & ~31);
#pragma unroll
    for (int b = 0; b < 4; b++) {
        *(__half2*)(phb + (b * 4 + u) * 2) =
            __halves2half2(__float2half_rn(v[2 * b]), __float2half_rn(v[2 * b + 1]));
    }
}

// ---------------- launch ----------------
extern "C" void kernel_launch(void* const* d_in, const int* in_sizes, int n_in,
                              void* d_out, int out_size)
{
    (void)in_sizes; (void)n_in; (void)out_size;
    const float* x  = (const float*)d_in[0];
    const float* Wk = (const float*)d_in[1];
    const float* Wq = (const float*)d_in[2];
    const float* Wv = (const float*)d_in[3];

    float* out = (float*)d_out;
    float* wei = out + (size_t)B_ * T_ * H_;

    __half *xh, *xl, *wqth, *wqtl, *wkth, *wktl, *mth, *mtl, *uh, *ul, *wvh, *vth, *weih;
    float* mtp;
    cudaGetSymbolAddress((void**)&xh, g_xh);     cudaGetSymbolAddress((void**)&xl, g_xl);
    cudaGetSymbolAddress((void**)&wqth, g_wqth); cudaGetSymbolAddress((void**)&wqtl, g_wqtl);
    cudaGetSymbolAddress((void**)&wkth, g_wkth); cudaGetSymbolAddress((void**)&wktl, g_wktl);
    cudaGetSymbolAddress((void**)&mtp, g_mtp);
    cudaGetSymbolAddress((void**)&mth, g_mth);   cudaGetSymbolAddress((void**)&mtl, g_mtl);
    cudaGetSymbolAddress((void**)&uh, g_uh);     cudaGetSymbolAddress((void**)&ul, g_ul);
    cudaGetSymbolAddress((void**)&wvh, g_wvh);
    cudaGetSymbolAddress((void**)&vth, g_vth);
    cudaGetSymbolAddress((void**)&weih, g_weih);

    static cudaStream_t sMt = nullptr, sV = nullptr, sB2 = nullptr;
    static cudaEvent_t evX0 = nullptr, evX = nullptr, evMt = nullptr, evV = nullptr,
                       evUA = nullptr, evB = nullptr;
    if (!sMt) {
        cudaStreamCreateWithFlags(&sMt, cudaStreamNonBlocking);
        cudaStreamCreateWithFlags(&sV,  cudaStreamNonBlocking);
        cudaStreamCreateWithFlags(&sB2, cudaStreamNonBlocking);
        cudaEventCreateWithFlags(&evX0, cudaEventDisableTiming);
        cudaEventCreateWithFlags(&evX,  cudaEventDisableTiming);
        cudaEventCreateWithFlags(&evMt, cudaEventDisableTiming);
        cudaEventCreateWithFlags(&evV,  cudaEventDisableTiming);
        cudaEventCreateWithFlags(&evUA, cudaEventDisableTiming);
        cudaEventCreateWithFlags(&evB,  cudaEventDisableTiming);
        cudaFuncSetAttribute(mma_nt<0,3>, cudaFuncAttributeMaxDynamicSharedMemorySize, GEMM_SMEM);
        cudaFuncSetAttribute(mma_nt<1,3>, cudaFuncAttributeMaxDynamicSharedMemorySize, GEMM_SMEM);
        cudaFuncSetAttribute(mma_nt<2,1>, cudaFuncAttributeMaxDynamicSharedMemorySize, GEMM_SMEM);
        cudaFuncSetAttribute(mma_nt<0,1>, cudaFuncAttributeMaxDynamicSharedMemorySize, GEMM_SMEM);
    }

    const dim3 blk(256);
    const long long sTT = (long long)T_ * T_;
    const long long sTC = (long long)T_ * C_;
    const long long sHT = (long long)H_ * T_;
    const long long sTH = (long long)T_ * H_;
    const int HB = B_ / 2;                 // 4 batches per half
    const long long oTC = HB * sTC, oTT = HB * sTT, oHT = HB * sHT, oTH = HB * sTH;

    // Fork origin -> sMt (Mt chain independent of x)
    cudaEventRecord(evX0, 0);
    cudaStreamWaitEvent(sMt, evX0, 0);
    {
        const dim3 gt(C_ / 32, H_ / 64, 2);
        transpose_split2_kernel<<<gt, blk, 0, sMt>>>(Wq, wqth, wqtl, Wk, wkth, wktl, H_, C_);
        const dim3 g(C_ / 128, C_ / 128, 4);
        mma_nt<0,3><<<g, blk, GEMM_SMEM, sMt>>>(wkth, wktl, wqth, wqtl, mtp, nullptr, nullptr,
                                                256, H_, H_, C_,
                                                256, 256, (long long)C_ * C_, 1.f, 0);
        mt_reduce_split<<<(C_ * C_ / 8 + 255) / 256, 256, 0, sMt>>>(mtp, mth, mtl, C_ * C_ / 8);
    }
    cudaEventRecord(evMt, sMt);

    // origin: split x
    {
        const int n8x = (B_ * T_ * C_) / 8;
        split_kernel<<<(n8x + 255) / 256, 256>>>(x, xh, xl, n8x);
    }
    cudaEventRecord(evX, 0);

    // sV: split Wv -> v GEMM
    cudaStreamWaitEvent(sV, evX, 0);
    {
        const int n8w = (H_ * C_) / 8;
        split_kernel<<<(n8w + 255) / 256, 256, 0, sV>>>(Wv, wvh, nullptr, n8w);
        const dim3 g(T_ / 128, H_ / 128, B_);
        mma_nt<2,1><<<g, blk, GEMM_SMEM, sV>>>(wvh, nullptr, xh, nullptr, nullptr, vth, nullptr,
                                               C_, C_, C_, T_, 0, sTC, sHT, 1.f, 0);
    }
    cudaEventRecord(evV, sV);

    // origin: u half A (batches 0..3 = tile rows 0..63), then u half B
    cudaStreamWaitEvent(0, evMt, 0);
    {
        const dim3 g(C_ / 128, (HB * T_) / 128, 1);
        mma_nt<1,3><<<g, blk, GEMM_SMEM>>>(xh, xl, mth, mtl, nullptr, uh, ul,
                                           C_, C_, C_, C_, 0, 0, 0, 1.f, 0);
    }
    cudaEventRecord(evUA, 0);
    {
        const dim3 g(C_ / 128, (HB * T_) / 128, 1);
        mma_nt<1,3><<<g, blk, GEMM_SMEM>>>(xh + oTC, xl + oTC, mth, mtl, nullptr,
                                           uh + oTC, ul + oTC,
                                           C_, C_, C_, C_, 0, 0, 0, 1.f, 0);
    }

    // sB2: half A pipeline (logits -> softmax -> out), starts right after u-A
    cudaStreamWaitEvent(sB2, evUA, 0);
    {
        const dim3 g(T_ / 128, T_ / 128, HB);
        mma_nt<0,3><<<g, blk, GEMM_SMEM, sB2>>>(uh, ul, xh, xl, wei, nullptr, nullptr,
                                                C_, C_, C_, T_, sTC, sTC, sTT, 0.03125f, 1);
        softmax_split_kernel<<<HB * T_, 256, 0, sB2>>>(wei, weih, T_);
        cudaStreamWaitEvent(sB2, evV, 0);
        const dim3 go(H_ / 128, T_ / 128, HB);
        mma_nt<0,1><<<go, blk, GEMM_SMEM, sB2>>>(weih, nullptr, vth, nullptr, out,
                                                 nullptr, nullptr,
                                                 T_, T_, T_, H_, sTT, sHT, sTH, 1.f, 2);
    }
    cudaEventRecord(evB, sB2);

    // origin: half B pipeline
    {
        const dim3 g(T_ / 128, T_ / 128, HB);
        mma_nt<0,3><<<g, blk, GEMM_SMEM>>>(uh + oTC, ul + oTC, xh + oTC, xl + oTC,
                                           wei + oTT, nullptr, nullptr,
                                           C_, C_, C_, T_, sTC, sTC, sTT, 0.03125f, 1);
        softmax_split_kernel<<<HB * T_, 256>>>(wei + oTT, weih + oTT, T_);
        cudaStreamWaitEvent(0, evV, 0);
        const dim3 go(H_ / 128, T_ / 128, HB);
        mma_nt<0,1><<<go, blk, GEMM_SMEM>>>(weih + oTT, nullptr, vth + oHT, nullptr,
                                            out + oTH, nullptr, nullptr,
                                            T_, T_, T_, H_, sTT, sHT, sTH, 1.f, 2);
    }

    // join
    cudaStreamWaitEvent(0, evB, 0);
}